// round 13
// baseline (speedup 1.0000x reference)
#include <cuda_runtime.h>
#include <cstdint>

// x: (B=8, C=512, T=16, W=28, H=28) fp32, contiguous.
// All three branches decompose onto 4x4x4 = 64 window maxes m4[tt][wi][hi]
// (window 4x7x7, stride 4x7x7); temporal multiply is identity (L=1):
//   out[0]      = max over all 64                      (n=1)
//   out[1+tt2]  = mean_{wi2,hi2} max over 2x2x2 block  (n=2)
//   out[3+tt]   = mean_{wi,hi}   m4s[tt][wi][hi]       (n=4)
// R12 post-mortem: warp-7 pipelining reverted. This round fuses row+window
// into one warp-local phase: warp w=(half,wi); lane l=(t',dw) covers one
// half-row; two shfl_xor max-reductions emit both m4s entries per warp.
// 2-deep cp.async pipeline, smem ~29.5 KB -> 7 blocks/SM (best packing).

#define SLICE     12544   // 16*28*28
#define TCHUNK    3136    // 4*28*28 (one temporal window-depth)
#define BUFPAD    608     // pad floats per buffer (occupancy shaping -> 7/SM)
#define BUFSTRIDE (TCHUNK + BUFPAD)
#define NBC       4096    // 8*512
#define NEG_INF   (-3.402823466e+38f)

__device__ __forceinline__ void cp_async16(uint32_t dst_smem, const void* src) {
    asm volatile("cp.async.cg.shared.global [%0], [%1], 16;\n"
                 :: "r"(dst_smem), "l"(src));
}
__device__ __forceinline__ void cp_commit() {
    asm volatile("cp.async.commit_group;\n" ::: "memory");
}
template <int N>
__device__ __forceinline__ void cp_wait() {
    asm volatile("cp.async.wait_group %0;\n" :: "n"(N) : "memory");
}

__global__ __launch_bounds__(256, 7)
void tmp3d_fused_kernel(const float* __restrict__ x, float* __restrict__ out) {
    __shared__ float tile[2 * BUFSTRIDE];   // 2 padded buffers: ~29.3 KB
    __shared__ float m4s[64];               // [tt*16 + wi*4 + hi]

    const int bc   = blockIdx.x;
    const int tid  = threadIdx.x;
    const int warp = tid >> 5;              // 0..7 -> (half = warp>>2, wi = warp&3)
    const int lane = tid & 31;
    const float* slice = x + bc * SLICE;

    const uint32_t tile_s = (uint32_t)__cvta_generic_to_shared(&tile[0]);

    // ---- prefetch: chunk c -> buffer b (784 x 16B LDGSTS) ----
    auto prefetch = [&](int c, int b) {
        const float* src = slice + c * TCHUNK;
        const uint32_t dst = tile_s + b * (BUFSTRIDE * 4);
        cp_async16(dst + tid * 16, src + tid * 4);
        cp_async16(dst + (tid + 256) * 16, src + (tid + 256) * 4);
        cp_async16(dst + (tid + 512) * 16, src + (tid + 512) * 4);
        if (tid < 784 - 768)
            cp_async16(dst + (tid + 768) * 16, src + (tid + 768) * 4);
        cp_commit();
    };

    prefetch(0, 0);
    prefetch(1, 1);

    const int half = warp >> 2;          // 0: hi{0,1}, 1: hi{2,3}
    const int wi   = warp & 3;
    const int tp   = lane / 7;           // t' 0..3  (lane < 28)
    const int dw   = lane - tp * 7;      // 0..6
    const int row  = tp * 28 + wi * 7 + dw;   // row index within chunk

    #pragma unroll
    for (int tc = 0; tc < 4; tc++) {
        // entering chunk tc, groups 0..tc+1 committed; wait_group 1 => tc landed
        if (tc == 3) cp_wait<0>(); else cp_wait<1>();
        __syncthreads();

        const float* buf = tile + (tc & 1) * BUFSTRIDE;

        // ---- fused row+window phase: all 8 warps identical work ----
        float ma = NEG_INF, mb = NEG_INF;
        if (lane < 28) {
            const float4* rp =
                reinterpret_cast<const float4*>(buf + row * 28 + half * 12);
            float4 v0 = rp[0], v1 = rp[1], v2 = rp[2], v3 = rp[3];
            if (half == 0) {
                // floats 0..15 of row: ma = max h0..6, mb = max h7..13
                ma = fmaxf(fmaxf(fmaxf(v0.x, v0.y), fmaxf(v0.z, v0.w)),
                           fmaxf(fmaxf(v1.x, v1.y), v1.z));
                mb = fmaxf(fmaxf(fmaxf(v1.w, v2.x), fmaxf(v2.y, v2.z)),
                           fmaxf(fmaxf(v2.w, v3.x), v3.y));
            } else {
                // floats 12..27 of row: ma = max h14..20, mb = max h21..27
                ma = fmaxf(fmaxf(fmaxf(v0.z, v0.w), fmaxf(v1.x, v1.y)),
                           fmaxf(fmaxf(v1.z, v1.w), v2.x));
                mb = fmaxf(fmaxf(fmaxf(v2.y, v2.z), fmaxf(v2.w, v3.x)),
                           fmaxf(fmaxf(v3.y, v3.z), v3.w));
            }
        }
        // warp max over the 28 contributing lanes (others hold -inf)
        #pragma unroll
        for (int off = 16; off > 0; off >>= 1) {
            ma = fmaxf(ma, __shfl_xor_sync(0xffffffffu, ma, off));
            mb = fmaxf(mb, __shfl_xor_sync(0xffffffffu, mb, off));
        }
        if (lane == 0) {
            m4s[tc * 16 + wi * 4 + 2 * half + 0] = ma;
            m4s[tc * 16 + wi * 4 + 2 * half + 1] = mb;
        }
        __syncthreads();   // all buffer reads done -> safe to overwrite

        // ---- keep the DMA stream rolling: prefetch chunk tc+2 ----
        if (tc < 2) prefetch(tc + 2, tc & 1);
    }
    __syncthreads();   // m4s complete

    // ---- finishing tree: 7 outputs ----
    if (tid < 7) {
        float r;
        if (tid == 0) {
            float m = m4s[0];
            #pragma unroll
            for (int i = 1; i < 64; i++) m = fmaxf(m, m4s[i]);
            r = m;
        } else if (tid < 3) {
            const int tt2 = tid - 1;
            float acc = 0.0f;
            #pragma unroll
            for (int wi2 = 0; wi2 < 2; wi2++) {
                #pragma unroll
                for (int hi2 = 0; hi2 < 2; hi2++) {
                    float m = NEG_INF;
                    #pragma unroll
                    for (int dt = 0; dt < 2; dt++)
                        #pragma unroll
                        for (int dw2 = 0; dw2 < 2; dw2++)
                            #pragma unroll
                            for (int dh = 0; dh < 2; dh++)
                                m = fmaxf(m, m4s[(2*tt2 + dt) * 16 +
                                                 (2*wi2 + dw2) * 4 + (2*hi2 + dh)]);
                    acc += m;
                }
            }
            r = acc * 0.25f;
        } else {
            const int tt = tid - 3;
            float acc = 0.0f;
            #pragma unroll
            for (int i = 0; i < 16; i++) acc += m4s[tt * 16 + i];
            r = acc * (1.0f / 16.0f);
        }
        out[bc * 7 + tid] = r;
    }
}

extern "C" void kernel_launch(void* const* d_in, const int* in_sizes, int n_in,
                              void* d_out, int out_size) {
    const float* x = (const float*)d_in[0];
    float* out = (float*)d_out;
    tmp3d_fused_kernel<<<NBC, 256>>>(x, out);
}

// round 14
// speedup vs baseline: 1.0299x; 1.0299x over previous
#include <cuda_runtime.h>
#include <cstdint>

// x: (B=8, C=512, T=16, W=28, H=28) fp32, contiguous.
// All three branches decompose onto 4x4x4 = 64 window maxes m4[tt][wi][hi]
// (window 4x7x7, stride 4x7x7); temporal multiply is identity (L=1):
//   out[0]      = max over all 64                      (n=1)
//   out[1+tt2]  = mean_{wi2,hi2} max over 2x2x2 block  (n=2)
//   out[3+tt]   = mean_{wi,hi}   m4s[tt][wi][hi]       (n=4)
// R13 post-mortem: shfl-fused phase reverted; R11 schedule restored
// (measured best: 33.4us kernel, DRAM 79.5%). Only change vs R11: window
// phase split across thread pairs (32 threads, 14 LDS each + 1 shfl)
// to halve the serial inter-barrier chain.
// Smem ~30.9 KB -> 7 blocks/SM -> 3.95 waves (best packing).

#define SLICE     12544   // 16*28*28
#define TCHUNK    3136    // 4*28*28 (one temporal window-depth)
#define BUFPAD    448     // pad floats per buffer (occupancy shaping -> 7/SM)
#define BUFSTRIDE (TCHUNK + BUFPAD)
#define NBC       4096    // 8*512
#define NEG_INF   (-3.402823466e+38f)

__device__ __forceinline__ void cp_async16(uint32_t dst_smem, const void* src) {
    asm volatile("cp.async.cg.shared.global [%0], [%1], 16;\n"
                 :: "r"(dst_smem), "l"(src));
}
__device__ __forceinline__ void cp_commit() {
    asm volatile("cp.async.commit_group;\n" ::: "memory");
}
template <int N>
__device__ __forceinline__ void cp_wait() {
    asm volatile("cp.async.wait_group %0;\n" :: "n"(N) : "memory");
}

__global__ __launch_bounds__(256, 7)
void tmp3d_fused_kernel(const float* __restrict__ x, float* __restrict__ out) {
    __shared__ float tile[2 * BUFSTRIDE];   // 2 padded buffers: ~28.7 KB
    __shared__ float pm[4][112];            // per-half-row partials [hi][t'*28+w]
    __shared__ float m4s[64];               // [tt*16 + wi*4 + hi]

    const int bc  = blockIdx.x;
    const int tid = threadIdx.x;
    const float* slice = x + bc * SLICE;

    const uint32_t tile_s = (uint32_t)__cvta_generic_to_shared(&tile[0]);

    // ---- prefetch: chunk c -> buffer b (784 x 16B LDGSTS) ----
    auto prefetch = [&](int c, int b) {
        const float* src = slice + c * TCHUNK;
        const uint32_t dst = tile_s + b * (BUFSTRIDE * 4);
        cp_async16(dst + tid * 16, src + tid * 4);
        cp_async16(dst + (tid + 256) * 16, src + (tid + 256) * 4);
        cp_async16(dst + (tid + 512) * 16, src + (tid + 512) * 4);
        if (tid < 784 - 768)
            cp_async16(dst + (tid + 768) * 16, src + (tid + 768) * 4);
        cp_commit();
    };

    prefetch(0, 0);
    prefetch(1, 1);

    #pragma unroll
    for (int tc = 0; tc < 4; tc++) {
        // entering chunk tc, groups 0..tc+1 committed; wait_group 1 => tc landed
        if (tc == 3) cp_wait<0>(); else cp_wait<1>();
        __syncthreads();

        const float* buf = tile + (tc & 1) * BUFSTRIDE;

        // ---- row phase: 224 threads, one half-row (14 floats) each ----
        // half 0 -> hi{0,1}, half 1 -> hi{2,3}. Conflict-free LDS.128.
        if (tid < 224) {
            const int half = tid / 112;          // 0 or 1
            const int r    = tid - half * 112;   // row index (t'*28 + w)
            const float4* rp =
                reinterpret_cast<const float4*>(buf + r * 28 + half * 12);
            float4 v0 = rp[0], v1 = rp[1], v2 = rp[2], v3 = rp[3];
            float ma, mb;
            if (half == 0) {
                ma = fmaxf(fmaxf(fmaxf(v0.x, v0.y), fmaxf(v0.z, v0.w)),
                           fmaxf(fmaxf(v1.x, v1.y), v1.z));
                mb = fmaxf(fmaxf(fmaxf(v1.w, v2.x), fmaxf(v2.y, v2.z)),
                           fmaxf(fmaxf(v2.w, v3.x), v3.y));
            } else {
                ma = fmaxf(fmaxf(fmaxf(v0.z, v0.w), fmaxf(v1.x, v1.y)),
                           fmaxf(fmaxf(v1.z, v1.w), v2.x));
                mb = fmaxf(fmaxf(fmaxf(v2.y, v2.z), fmaxf(v2.w, v3.x)),
                           fmaxf(fmaxf(v3.y, v3.z), v3.w));
            }
            pm[2 * half + 0][r] = ma;
            pm[2 * half + 1][r] = mb;
        }
        __syncthreads();   // pm ready AND all buffer reads done

        // ---- keep the DMA stream rolling: prefetch chunk tc+2 ----
        if (tc < 2) prefetch(tc + 2, tc & 1);

        // ---- window phase: 16 windows, one thread PAIR each (32 threads) ----
        // thread (2k+j) reduces t' in {2j, 2j+1}; pair combined via shfl.
        if (tid < 32) {
            const int w16 = tid >> 1;       // window 0..15
            const int j   = tid & 1;        // which t' pair
            const int wi  = w16 >> 2;
            const int hi  = w16 & 3;
            const float* p = &pm[hi][wi * 7];
            float m = NEG_INF;
            #pragma unroll
            for (int t = 0; t < 2; t++) {
                const float* pt = p + (2 * j + t) * 28;
                #pragma unroll
                for (int dw = 0; dw < 7; dw++)
                    m = fmaxf(m, pt[dw]);
            }
            m = fmaxf(m, __shfl_xor_sync(0xffffffffu, m, 1));
            if (j == 0)
                m4s[tc * 16 + wi * 4 + hi] = m;
        }
        // next iteration's top __syncthreads orders window pm-reads
        // before the next row phase overwrites pm.
    }
    __syncthreads();   // m4s complete

    // ---- finishing tree: 7 outputs ----
    if (tid < 7) {
        float r;
        if (tid == 0) {
            float m = m4s[0];
            #pragma unroll
            for (int i = 1; i < 64; i++) m = fmaxf(m, m4s[i]);
            r = m;
        } else if (tid < 3) {
            const int tt2 = tid - 1;
            float acc = 0.0f;
            #pragma unroll
            for (int wi2 = 0; wi2 < 2; wi2++) {
                #pragma unroll
                for (int hi2 = 0; hi2 < 2; hi2++) {
                    float m = NEG_INF;
                    #pragma unroll
                    for (int dt = 0; dt < 2; dt++)
                        #pragma unroll
                        for (int dw = 0; dw < 2; dw++)
                            #pragma unroll
                            for (int dh = 0; dh < 2; dh++)
                                m = fmaxf(m, m4s[(2*tt2 + dt) * 16 +
                                                 (2*wi2 + dw) * 4 + (2*hi2 + dh)]);
                    acc += m;
                }
            }
            r = acc * 0.25f;
        } else {
            const int tt = tid - 3;
            float acc = 0.0f;
            #pragma unroll
            for (int i = 0; i < 16; i++) acc += m4s[tt * 16 + i];
            r = acc * (1.0f / 16.0f);
        }
        out[bc * 7 + tid] = r;
    }
}

extern "C" void kernel_launch(void* const* d_in, const int* in_sizes, int n_in,
                              void* d_out, int out_size) {
    const float* x = (const float*)d_in[0];
    float* out = (float*)d_out;
    tmp3d_fused_kernel<<<NBC, 256>>>(x, out);
}